// round 1
// baseline (speedup 1.0000x reference)
#include <cuda_runtime.h>

// Problem shapes (fixed by the dataset)
#define BSZ  8
#define ENL  512   // encoder length
#define DEL  64    // decoder length
#define EDIM 512   // embedding
#define UDIM 512   // units
#define TDIM 100   // topics
#define JT   4     // decoder positions per block in fused kernel

// Scratch (no cudaMalloc allowed)
__device__ float g_aeT[BSZ * UDIM * ENL];   // att_en transposed: [b][u][i]  (8 MB)
__device__ float g_c  [BSZ * DEL * UDIM];   // att_de + topic bias: [b][j][u] (1 MB)
__device__ float g_tw [BSZ * UDIM];         // topic bias [b][u]

__device__ __forceinline__ float tanh_fast(float x) {
    float y;
    asm("tanh.approx.f32 %0, %1;" : "=f"(y) : "f"(x));
    return y;
}

// ---------------------------------------------------------------------------
// Kernel 1: g_aeT[b][u][i] = sum_e en[b][i][e] * w_en[e][u]
// Tiled SGEMM, 64x64 tile, Ktile=16, 256 threads, 4x4 per thread.
// ---------------------------------------------------------------------------
__global__ void __launch_bounds__(256) k_gemm_aeT(
    const float* __restrict__ en, const float* __restrict__ w_en)
{
    const int b  = blockIdx.z;
    const int u0 = blockIdx.y * 64;
    const int i0 = blockIdx.x * 64;
    __shared__ float As[16][65];  // [e][u]
    __shared__ float Bs[16][65];  // [e][i]
    const float* enb = en + (size_t)b * ENL * EDIM;
    const int tid = threadIdx.x;
    const int tu = tid & 15;   // u micro-tile index
    const int ti = tid >> 4;   // i micro-tile index
    float acc[4][4] = {};

    for (int e0 = 0; e0 < EDIM; e0 += 16) {
        #pragma unroll
        for (int r = 0; r < 4; r++) {
            int l = tid + 256 * r;
            int e = l >> 6, uu = l & 63;
            As[e][uu] = w_en[(size_t)(e0 + e) * UDIM + u0 + uu];
        }
        #pragma unroll
        for (int r = 0; r < 4; r++) {
            int l = tid + 256 * r;
            int e = l & 15, ii = l >> 4;
            Bs[e][ii] = enb[(size_t)(i0 + ii) * EDIM + e0 + e];
        }
        __syncthreads();
        #pragma unroll
        for (int k = 0; k < 16; k++) {
            float a[4], bb[4];
            #pragma unroll
            for (int r = 0; r < 4; r++) a[r] = As[k][tu * 4 + r];
            #pragma unroll
            for (int c = 0; c < 4; c++) bb[c] = Bs[k][ti * 4 + c];
            #pragma unroll
            for (int r = 0; r < 4; r++)
                #pragma unroll
                for (int c = 0; c < 4; c++)
                    acc[r][c] = fmaf(a[r], bb[c], acc[r][c]);
        }
        __syncthreads();
    }
    float* outp = g_aeT + (size_t)b * UDIM * ENL;
    #pragma unroll
    for (int r = 0; r < 4; r++)
        #pragma unroll
        for (int c = 0; c < 4; c++)
            outp[(size_t)(u0 + tu * 4 + r) * ENL + i0 + ti * 4 + c] = acc[r][c];
}

// ---------------------------------------------------------------------------
// Kernel 2a: g_tw[b][u] = sum_t topics[b][t] * wt[u][t]   (wt is [E=512, T=100])
// ---------------------------------------------------------------------------
__global__ void __launch_bounds__(512) k_tw(
    const float* __restrict__ topics, const float* __restrict__ wt)
{
    const int b = blockIdx.x;
    const int u = threadIdx.x;
    __shared__ float ts[TDIM];
    if (u < TDIM) ts[u] = topics[b * TDIM + u];
    __syncthreads();
    float acc = 0.f;
    #pragma unroll 4
    for (int t = 0; t < TDIM; t++)
        acc = fmaf(ts[t], wt[u * TDIM + t], acc);
    g_tw[b * UDIM + u] = acc;
}

// ---------------------------------------------------------------------------
// Kernel 2b: g_c[b][j][u] = sum_e de[b][j][e] * w_de[e][u] + g_tw[b][u]
// Tile: 64(j) x 64(u), Ktile=16, 256 threads, 4x4 per thread.
// ---------------------------------------------------------------------------
__global__ void __launch_bounds__(256) k_c(
    const float* __restrict__ de, const float* __restrict__ w_de)
{
    const int b  = blockIdx.y;
    const int u0 = blockIdx.x * 64;
    __shared__ float As[16][65];  // [e][j]
    __shared__ float Bs[16][65];  // [e][u]
    const float* deb = de + (size_t)b * DEL * EDIM;
    const int tid = threadIdx.x;
    const int tj = tid & 15;
    const int tu = tid >> 4;
    float acc[4][4] = {};

    for (int e0 = 0; e0 < EDIM; e0 += 16) {
        #pragma unroll
        for (int r = 0; r < 4; r++) {
            int l = tid + 256 * r;
            int e = l & 15, j = l >> 4;
            As[e][j] = deb[(size_t)j * EDIM + e0 + e];
        }
        #pragma unroll
        for (int r = 0; r < 4; r++) {
            int l = tid + 256 * r;
            int e = l >> 6, uu = l & 63;
            Bs[e][uu] = w_de[(size_t)(e0 + e) * UDIM + u0 + uu];
        }
        __syncthreads();
        #pragma unroll
        for (int k = 0; k < 16; k++) {
            float a[4], bb[4];
            #pragma unroll
            for (int r = 0; r < 4; r++) a[r] = As[k][tj * 4 + r];
            #pragma unroll
            for (int c = 0; c < 4; c++) bb[c] = Bs[k][tu * 4 + c];
            #pragma unroll
            for (int r = 0; r < 4; r++)
                #pragma unroll
                for (int c = 0; c < 4; c++)
                    acc[r][c] = fmaf(a[r], bb[c], acc[r][c]);
        }
        __syncthreads();
    }
    #pragma unroll
    for (int r = 0; r < 4; r++)
        #pragma unroll
        for (int c = 0; c < 4; c++) {
            int j = tj * 4 + r;
            int u = u0 + tu * 4 + c;
            g_c[((size_t)b * DEL + j) * UDIM + u] = acc[r][c] + g_tw[b * UDIM + u];
        }
}

// ---------------------------------------------------------------------------
// Kernel 3 (fused): for a block of (b, j0..j0+3):
//   mu[j][i]   = sum_u tanh(aeT[b][u][i] + c[b][j][u]) * nu[u]
//   alphas     = softmax_i(mu);  p_gen = sigmoid(mu)
//   output[j]  = de[b][j] + alphas @ en[b]
// 512 threads: thread t owns encoder position i=t in phase 1, embedding e=t in phase 2.
// ---------------------------------------------------------------------------
__global__ void __launch_bounds__(512) k_attn(
    const float* __restrict__ en, const float* __restrict__ de,
    const float* __restrict__ nu, float* __restrict__ out)
{
    const int b  = blockIdx.y;
    const int j0 = blockIdx.x * JT;
    const int t  = threadIdx.x;

    __shared__ float4 cs[UDIM];    // c for 4 j's, transposed: cs[u] = (c[j0..j0+3][u])
    __shared__ float  nus[UDIM];
    __shared__ float4 red4[16];
    __shared__ float4 alph[ENL];   // alphas for 4 j's: alph[i] = (a_j0..a_j0+3)

    const float* cb = g_c + ((size_t)b * DEL + j0) * UDIM;
    cs[t]  = make_float4(cb[t], cb[UDIM + t], cb[2 * UDIM + t], cb[3 * UDIM + t]);
    nus[t] = nu[t];
    __syncthreads();

    // Phase 1: mu for i = t, all 4 j's.  aeT column t is coalesced across threads.
    const float* ae = g_aeT + (size_t)b * UDIM * ENL + t;
    float m0 = 0.f, m1 = 0.f, m2 = 0.f, m3 = 0.f;
    #pragma unroll 4
    for (int u = 0; u < UDIM; u++) {
        float a  = ae[(size_t)u * ENL];
        float4 c4 = cs[u];
        float nv  = nus[u];
        m0 = fmaf(nv, tanh_fast(a + c4.x), m0);
        m1 = fmaf(nv, tanh_fast(a + c4.y), m1);
        m2 = fmaf(nv, tanh_fast(a + c4.z), m2);
        m3 = fmaf(nv, tanh_fast(a + c4.w), m3);
    }

    const int wid = t >> 5, lane = t & 31;

    // Block max (4 lanes at once)
    float4 r = make_float4(m0, m1, m2, m3);
    #pragma unroll
    for (int o = 16; o; o >>= 1) {
        r.x = fmaxf(r.x, __shfl_xor_sync(0xffffffffu, r.x, o));
        r.y = fmaxf(r.y, __shfl_xor_sync(0xffffffffu, r.y, o));
        r.z = fmaxf(r.z, __shfl_xor_sync(0xffffffffu, r.z, o));
        r.w = fmaxf(r.w, __shfl_xor_sync(0xffffffffu, r.w, o));
    }
    if (lane == 0) red4[wid] = r;
    __syncthreads();
    float4 M = red4[0];
    #pragma unroll
    for (int w = 1; w < 16; w++) {
        float4 q = red4[w];
        M.x = fmaxf(M.x, q.x); M.y = fmaxf(M.y, q.y);
        M.z = fmaxf(M.z, q.z); M.w = fmaxf(M.w, q.w);
    }
    __syncthreads();  // before reusing red4

    float e0 = __expf(m0 - M.x);
    float e1 = __expf(m1 - M.y);
    float e2 = __expf(m2 - M.z);
    float e3 = __expf(m3 - M.w);

    // Block sum
    float4 s = make_float4(e0, e1, e2, e3);
    #pragma unroll
    for (int o = 16; o; o >>= 1) {
        s.x += __shfl_xor_sync(0xffffffffu, s.x, o);
        s.y += __shfl_xor_sync(0xffffffffu, s.y, o);
        s.z += __shfl_xor_sync(0xffffffffu, s.z, o);
        s.w += __shfl_xor_sync(0xffffffffu, s.w, o);
    }
    if (lane == 0) red4[wid] = s;
    __syncthreads();
    float4 S = red4[0];
    #pragma unroll
    for (int w = 1; w < 16; w++) {
        float4 q = red4[w];
        S.x += q.x; S.y += q.y; S.z += q.z; S.w += q.w;
    }

    float a0 = e0 / S.x, a1 = e1 / S.y, a2 = e2 / S.z, a3 = e3 / S.w;
    alph[t] = make_float4(a0, a1, a2, a3);

    // Output layout (flat tuple): [output(262144) | alphas(262144) | p_gen(262144)]
    float* alphas_out = out + BSZ * DEL * ENL;
    float* pgen_out   = out + 2 * BSZ * DEL * ENL;
    const int base = ((b * DEL + j0) * ENL) + t;
    alphas_out[base          ] = a0;
    alphas_out[base +     ENL] = a1;
    alphas_out[base + 2 * ENL] = a2;
    alphas_out[base + 3 * ENL] = a3;
    pgen_out[base          ] = 1.f / (1.f + __expf(-m0));
    pgen_out[base +     ENL] = 1.f / (1.f + __expf(-m1));
    pgen_out[base + 2 * ENL] = 1.f / (1.f + __expf(-m2));
    pgen_out[base + 3 * ENL] = 1.f / (1.f + __expf(-m3));
    __syncthreads();

    // Phase 2: sum_en[j][e=t] = sum_i alphas[j][i] * en[b][i][e]
    float s0 = 0.f, s1 = 0.f, s2 = 0.f, s3 = 0.f;
    const float* enb = en + (size_t)b * ENL * EDIM + t;
    #pragma unroll 4
    for (int i = 0; i < ENL; i++) {
        float ev  = enb[(size_t)i * EDIM];
        float4 av = alph[i];
        s0 = fmaf(av.x, ev, s0);
        s1 = fmaf(av.y, ev, s1);
        s2 = fmaf(av.z, ev, s2);
        s3 = fmaf(av.w, ev, s3);
    }
    const int ob = ((b * DEL + j0) * EDIM) + t;
    out[ob           ] = de[ob           ] + s0;
    out[ob +     EDIM] = de[ob +     EDIM] + s1;
    out[ob + 2 * EDIM] = de[ob + 2 * EDIM] + s2;
    out[ob + 3 * EDIM] = de[ob + 3 * EDIM] + s3;
}

// ---------------------------------------------------------------------------
extern "C" void kernel_launch(void* const* d_in, const int* in_sizes, int n_in,
                              void* d_out, int out_size)
{
    const float* en     = (const float*)d_in[0];
    const float* de     = (const float*)d_in[1];
    const float* topics = (const float*)d_in[2];
    const float* w_en   = (const float*)d_in[3];
    const float* w_de   = (const float*)d_in[4];
    const float* nu     = (const float*)d_in[5];
    const float* wt     = (const float*)d_in[6];
    float* out = (float*)d_out;

    k_gemm_aeT<<<dim3(ENL / 64, UDIM / 64, BSZ), 256>>>(en, w_en);
    k_tw<<<BSZ, UDIM>>>(topics, wt);
    k_c<<<dim3(UDIM / 64, BSZ), 256>>>(de, w_de);
    k_attn<<<dim3(DEL / JT, BSZ), 512>>>(en, de, nu, out);
}

// round 2
// speedup vs baseline: 1.2138x; 1.2138x over previous
#include <cuda_runtime.h>

// Problem shapes (fixed by the dataset)
#define BSZ  8
#define ENL  512   // encoder length
#define DEL  64    // decoder length
#define EDIM 512   // embedding
#define UDIM 512   // units
#define TDIM 100   // topics
#define JT   2     // decoder positions per block in fused kernel

// Scratch (no cudaMalloc allowed)
__device__ float g_aeT[BSZ * UDIM * ENL];   // att_en transposed: [b][u][i]  (8 MB)
__device__ float g_c  [BSZ * DEL * UDIM];   // att_de + topic bias: [b][j][u] (1 MB)
__device__ float g_tw [BSZ * UDIM];         // topic bias [b][u]

typedef unsigned long long ull;

__device__ __forceinline__ float tanh_fast(float x) {
    float y;
    asm("tanh.approx.f32 %0, %1;" : "=f"(y) : "f"(x));
    return y;
}
__device__ __forceinline__ ull pack2(float x, float y) {
    ull r; asm("mov.b64 %0, {%1, %2};" : "=l"(r) : "f"(x), "f"(y)); return r;
}
__device__ __forceinline__ void unpack2(ull p, float& x, float& y) {
    asm("mov.b64 {%0, %1}, %2;" : "=f"(x), "=f"(y) : "l"(p));
}
__device__ __forceinline__ ull fma2(ull a, ull b, ull c) {
    ull d; asm("fma.rn.f32x2 %0, %1, %2, %3;" : "=l"(d) : "l"(a), "l"(b), "l"(c));
    return d;
}

// ---------------------------------------------------------------------------
// Kernel 1: g_aeT[b][u][i] = sum_e en[b][i][e] * w_en[e][u]
// Tiled SGEMM, 64x64 tile, Ktile=16, 256 threads, 4x4 per thread,
// packed fma.rn.f32x2 accumulators (2x fp32 FMA rate on sm_103a).
// ---------------------------------------------------------------------------
__global__ void __launch_bounds__(256) k_gemm_aeT(
    const float* __restrict__ en, const float* __restrict__ w_en)
{
    const int b  = blockIdx.z;
    const int u0 = blockIdx.y * 64;
    const int i0 = blockIdx.x * 64;
    __shared__ float As[16][68];  // [e][u]  (row stride 272B: 16B-aligned)
    __shared__ float Bs[16][68];  // [e][i]
    const float* enb = en + (size_t)b * ENL * EDIM;
    const int tid = threadIdx.x;
    const int tu = tid & 15;   // u micro-tile index
    const int ti = tid >> 4;   // i micro-tile index
    ull acc2[4][2] = {};       // acc2[r][cp] = (acc[r][2cp], acc[r][2cp+1])

    for (int e0 = 0; e0 < EDIM; e0 += 16) {
        #pragma unroll
        for (int r = 0; r < 4; r++) {
            int l = tid + 256 * r;
            int e = l >> 6, uu = l & 63;
            As[e][uu] = w_en[(size_t)(e0 + e) * UDIM + u0 + uu];
        }
        #pragma unroll
        for (int r = 0; r < 4; r++) {
            int l = tid + 256 * r;
            int e = l & 15, ii = l >> 4;
            Bs[e][ii] = enb[(size_t)(i0 + ii) * EDIM + e0 + e];
        }
        __syncthreads();
        #pragma unroll
        for (int k = 0; k < 16; k++) {
            const float4 av = *(const float4*)&As[k][tu * 4];
            const ull b01 = *(const ull*)&Bs[k][ti * 4];
            const ull b23 = *(const ull*)&Bs[k][ti * 4 + 2];
            ull pa0 = pack2(av.x, av.x), pa1 = pack2(av.y, av.y);
            ull pa2 = pack2(av.z, av.z), pa3 = pack2(av.w, av.w);
            acc2[0][0] = fma2(pa0, b01, acc2[0][0]); acc2[0][1] = fma2(pa0, b23, acc2[0][1]);
            acc2[1][0] = fma2(pa1, b01, acc2[1][0]); acc2[1][1] = fma2(pa1, b23, acc2[1][1]);
            acc2[2][0] = fma2(pa2, b01, acc2[2][0]); acc2[2][1] = fma2(pa2, b23, acc2[2][1]);
            acc2[3][0] = fma2(pa3, b01, acc2[3][0]); acc2[3][1] = fma2(pa3, b23, acc2[3][1]);
        }
        __syncthreads();
    }
    float* outp = g_aeT + (size_t)b * UDIM * ENL;
    #pragma unroll
    for (int r = 0; r < 4; r++) {
        float v0, v1, v2, v3;
        unpack2(acc2[r][0], v0, v1);
        unpack2(acc2[r][1], v2, v3);
        float* row = outp + (size_t)(u0 + tu * 4 + r) * ENL + i0 + ti * 4;
        row[0] = v0; row[1] = v1; row[2] = v2; row[3] = v3;
    }
}

// ---------------------------------------------------------------------------
// Kernel 2a: g_tw[b][u] = sum_t topics[b][t] * wt[u][t]   (wt is [512, 100])
// ---------------------------------------------------------------------------
__global__ void __launch_bounds__(512) k_tw(
    const float* __restrict__ topics, const float* __restrict__ wt)
{
    const int b = blockIdx.x;
    const int u = threadIdx.x;
    __shared__ float ts[TDIM];
    if (u < TDIM) ts[u] = topics[b * TDIM + u];
    __syncthreads();
    float acc = 0.f;
    #pragma unroll 4
    for (int t = 0; t < TDIM; t++)
        acc = fmaf(ts[t], wt[u * TDIM + t], acc);
    g_tw[b * UDIM + u] = acc;
}

// ---------------------------------------------------------------------------
// Kernel 2b: g_c[b][j][u] = sum_e de[b][j][e] * w_de[e][u] + g_tw[b][u]
// ---------------------------------------------------------------------------
__global__ void __launch_bounds__(256) k_c(
    const float* __restrict__ de, const float* __restrict__ w_de)
{
    const int b  = blockIdx.y;
    const int u0 = blockIdx.x * 64;
    __shared__ float As[16][68];  // [e][j]
    __shared__ float Bs[16][68];  // [e][u]
    const float* deb = de + (size_t)b * DEL * EDIM;
    const int tid = threadIdx.x;
    const int tj = tid & 15;
    const int tu = tid >> 4;
    ull acc2[4][2] = {};

    for (int e0 = 0; e0 < EDIM; e0 += 16) {
        #pragma unroll
        for (int r = 0; r < 4; r++) {
            int l = tid + 256 * r;
            int e = l & 15, j = l >> 4;
            As[e][j] = deb[(size_t)j * EDIM + e0 + e];
        }
        #pragma unroll
        for (int r = 0; r < 4; r++) {
            int l = tid + 256 * r;
            int e = l >> 6, uu = l & 63;
            Bs[e][uu] = w_de[(size_t)(e0 + e) * UDIM + u0 + uu];
        }
        __syncthreads();
        #pragma unroll
        for (int k = 0; k < 16; k++) {
            const float4 av = *(const float4*)&As[k][tj * 4];
            const ull b01 = *(const ull*)&Bs[k][tu * 4];
            const ull b23 = *(const ull*)&Bs[k][tu * 4 + 2];
            ull pa0 = pack2(av.x, av.x), pa1 = pack2(av.y, av.y);
            ull pa2 = pack2(av.z, av.z), pa3 = pack2(av.w, av.w);
            acc2[0][0] = fma2(pa0, b01, acc2[0][0]); acc2[0][1] = fma2(pa0, b23, acc2[0][1]);
            acc2[1][0] = fma2(pa1, b01, acc2[1][0]); acc2[1][1] = fma2(pa1, b23, acc2[1][1]);
            acc2[2][0] = fma2(pa2, b01, acc2[2][0]); acc2[2][1] = fma2(pa2, b23, acc2[2][1]);
            acc2[3][0] = fma2(pa3, b01, acc2[3][0]); acc2[3][1] = fma2(pa3, b23, acc2[3][1]);
        }
        __syncthreads();
    }
    #pragma unroll
    for (int r = 0; r < 4; r++) {
        float v[4];
        unpack2(acc2[r][0], v[0], v[1]);
        unpack2(acc2[r][1], v[2], v[3]);
        int j = tj * 4 + r;
        #pragma unroll
        for (int c = 0; c < 4; c++) {
            int u = u0 + tu * 4 + c;
            g_c[((size_t)b * DEL + j) * UDIM + u] = v[c] + g_tw[b * UDIM + u];
        }
    }
}

// ---------------------------------------------------------------------------
// Kernel 3 (fused): block = (b, j0..j0+1):
//   mu[j][i]   = sum_u tanh(aeT[b][u][i] + c[b][j][u]) * nu[u]
//   alphas     = softmax_i(mu);  p_gen = sigmoid(mu)
//   output[j]  = de[b][j] + alphas @ en[b]
// 512 threads, grid 256 blocks (2 blocks/SM target).
// ---------------------------------------------------------------------------
__global__ void __launch_bounds__(512) k_attn(
    const float* __restrict__ en, const float* __restrict__ de,
    const float* __restrict__ nu, float* __restrict__ out)
{
    const int b  = blockIdx.y;
    const int j0 = blockIdx.x * JT;
    const int t  = threadIdx.x;

    __shared__ float4 css[UDIM];   // (c[j0][u], c[j0+1][u], nu[u], 0)
    __shared__ float2 red2[16];
    __shared__ float2 alph[ENL];

    const float* cb = g_c + ((size_t)b * DEL + j0) * UDIM;
    css[t] = make_float4(cb[t], cb[UDIM + t], nu[t], 0.f);
    __syncthreads();

    // Phase 1: mu for i = t, 2 j's. Coalesced aeT column loads.
    const float* ae = g_aeT + (size_t)b * UDIM * ENL + t;
    float m0 = 0.f, m1 = 0.f;
    #pragma unroll 8
    for (int u = 0; u < UDIM; u++) {
        float a   = ae[(size_t)u * ENL];
        float4 c4 = css[u];
        m0 = fmaf(c4.z, tanh_fast(a + c4.x), m0);
        m1 = fmaf(c4.z, tanh_fast(a + c4.y), m1);
    }

    const int wid = t >> 5, lane = t & 31;

    // Block max
    float2 r = make_float2(m0, m1);
    #pragma unroll
    for (int o = 16; o; o >>= 1) {
        r.x = fmaxf(r.x, __shfl_xor_sync(0xffffffffu, r.x, o));
        r.y = fmaxf(r.y, __shfl_xor_sync(0xffffffffu, r.y, o));
    }
    if (lane == 0) red2[wid] = r;
    __syncthreads();
    float2 M = red2[0];
    #pragma unroll
    for (int w = 1; w < 16; w++) {
        float2 q = red2[w];
        M.x = fmaxf(M.x, q.x); M.y = fmaxf(M.y, q.y);
    }
    __syncthreads();  // before reusing red2

    float e0 = __expf(m0 - M.x);
    float e1 = __expf(m1 - M.y);

    // Block sum
    float2 s = make_float2(e0, e1);
    #pragma unroll
    for (int o = 16; o; o >>= 1) {
        s.x += __shfl_xor_sync(0xffffffffu, s.x, o);
        s.y += __shfl_xor_sync(0xffffffffu, s.y, o);
    }
    if (lane == 0) red2[wid] = s;
    __syncthreads();
    float2 S = red2[0];
    #pragma unroll
    for (int w = 1; w < 16; w++) {
        float2 q = red2[w];
        S.x += q.x; S.y += q.y;
    }

    float a0 = e0 / S.x, a1 = e1 / S.y;
    alph[t] = make_float2(a0, a1);

    // Output layout (flat tuple): [output | alphas | p_gen], each BSZ*DEL*{ENL|EDIM}
    float* alphas_out = out + BSZ * DEL * ENL;
    float* pgen_out   = out + 2 * BSZ * DEL * ENL;
    const int base = ((b * DEL + j0) * ENL) + t;
    alphas_out[base      ] = a0;
    alphas_out[base + ENL] = a1;
    pgen_out[base      ] = 1.f / (1.f + __expf(-m0));
    pgen_out[base + ENL] = 1.f / (1.f + __expf(-m1));
    __syncthreads();

    // Phase 2: sum_en[j][e=t] = sum_i alphas[j][i] * en[b][i][e]
    float s0 = 0.f, s1 = 0.f;
    const float* enb = en + (size_t)b * ENL * EDIM + t;
    #pragma unroll 8
    for (int i = 0; i < ENL; i++) {
        float ev  = enb[(size_t)i * EDIM];
        float2 av = alph[i];
        s0 = fmaf(av.x, ev, s0);
        s1 = fmaf(av.y, ev, s1);
    }
    const int ob = ((b * DEL + j0) * EDIM) + t;
    out[ob       ] = de[ob       ] + s0;
    out[ob + EDIM] = de[ob + EDIM] + s1;
}

// ---------------------------------------------------------------------------
extern "C" void kernel_launch(void* const* d_in, const int* in_sizes, int n_in,
                              void* d_out, int out_size)
{
    const float* en     = (const float*)d_in[0];
    const float* de     = (const float*)d_in[1];
    const float* topics = (const float*)d_in[2];
    const float* w_en   = (const float*)d_in[3];
    const float* w_de   = (const float*)d_in[4];
    const float* nu     = (const float*)d_in[5];
    const float* wt     = (const float*)d_in[6];
    float* out = (float*)d_out;

    k_gemm_aeT<<<dim3(ENL / 64, UDIM / 64, BSZ), 256>>>(en, w_en);
    k_tw<<<BSZ, UDIM>>>(topics, wt);
    k_c<<<dim3(UDIM / 64, BSZ), 256>>>(de, w_de);
    k_attn<<<dim3(DEL / JT, BSZ), 512>>>(en, de, nu, out);
}

// round 3
// speedup vs baseline: 1.2786x; 1.0533x over previous
#include <cuda_runtime.h>

// Problem shapes (fixed by the dataset)
#define BSZ  8
#define ENL  512   // encoder length
#define DEL  64    // decoder length
#define EDIM 512   // embedding
#define UDIM 512   // units
#define TDIM 100   // topics
#define JT   2     // decoder positions per block in fused kernel
#define STRIP 16   // load batching depth (MLP)

// Scratch (no cudaMalloc allowed)
__device__ float g_aeT[BSZ * UDIM * ENL];   // att_en transposed: [b][u][i]  (8 MB)
__device__ float g_c  [BSZ * DEL * UDIM];   // att_de + topic bias: [b][j][u] (1 MB)

typedef unsigned long long ull;

__device__ __forceinline__ float tanh_fast(float x) {
    float y;
    asm("tanh.approx.f32 %0, %1;" : "=f"(y) : "f"(x));
    return y;
}
__device__ __forceinline__ ull pack2(float x, float y) {
    ull r; asm("mov.b64 %0, {%1, %2};" : "=l"(r) : "f"(x), "f"(y)); return r;
}
__device__ __forceinline__ void unpack2(ull p, float& x, float& y) {
    asm("mov.b64 {%0, %1}, %2;" : "=f"(x), "=f"(y) : "l"(p));
}
__device__ __forceinline__ ull fma2(ull a, ull b, ull c) {
    ull d; asm("fma.rn.f32x2 %0, %1, %2, %3;" : "=l"(d) : "l"(a), "l"(b), "l"(c));
    return d;
}

// ---------------------------------------------------------------------------
// Kernel 1: g_aeT[b][u][i] = sum_e en[b][i][e] * w_en[e][u]
// Tiled SGEMM, 64x64 tile, Ktile=16, 256 threads, 4x4 per thread, f32x2 FMAs.
// ---------------------------------------------------------------------------
__global__ void __launch_bounds__(256) k_gemm_aeT(
    const float* __restrict__ en, const float* __restrict__ w_en)
{
    const int b  = blockIdx.z;
    const int u0 = blockIdx.y * 64;
    const int i0 = blockIdx.x * 64;
    __shared__ float As[16][68];  // [e][u]
    __shared__ float Bs[16][68];  // [e][i]
    const float* enb = en + (size_t)b * ENL * EDIM;
    const int tid = threadIdx.x;
    const int tu = tid & 15;
    const int ti = tid >> 4;
    ull acc2[4][2] = {};

    for (int e0 = 0; e0 < EDIM; e0 += 16) {
        #pragma unroll
        for (int r = 0; r < 4; r++) {
            int l = tid + 256 * r;
            int e = l >> 6, uu = l & 63;
            As[e][uu] = w_en[(size_t)(e0 + e) * UDIM + u0 + uu];
        }
        #pragma unroll
        for (int r = 0; r < 4; r++) {
            int l = tid + 256 * r;
            int e = l & 15, ii = l >> 4;
            Bs[e][ii] = enb[(size_t)(i0 + ii) * EDIM + e0 + e];
        }
        __syncthreads();
        #pragma unroll
        for (int k = 0; k < 16; k++) {
            const float4 av = *(const float4*)&As[k][tu * 4];
            const ull b01 = *(const ull*)&Bs[k][ti * 4];
            const ull b23 = *(const ull*)&Bs[k][ti * 4 + 2];
            ull pa0 = pack2(av.x, av.x), pa1 = pack2(av.y, av.y);
            ull pa2 = pack2(av.z, av.z), pa3 = pack2(av.w, av.w);
            acc2[0][0] = fma2(pa0, b01, acc2[0][0]); acc2[0][1] = fma2(pa0, b23, acc2[0][1]);
            acc2[1][0] = fma2(pa1, b01, acc2[1][0]); acc2[1][1] = fma2(pa1, b23, acc2[1][1]);
            acc2[2][0] = fma2(pa2, b01, acc2[2][0]); acc2[2][1] = fma2(pa2, b23, acc2[2][1]);
            acc2[3][0] = fma2(pa3, b01, acc2[3][0]); acc2[3][1] = fma2(pa3, b23, acc2[3][1]);
        }
        __syncthreads();
    }
    float* outp = g_aeT + (size_t)b * UDIM * ENL;
    #pragma unroll
    for (int r = 0; r < 4; r++) {
        float v0, v1, v2, v3;
        unpack2(acc2[r][0], v0, v1);
        unpack2(acc2[r][1], v2, v3);
        float* row = outp + (size_t)(u0 + tu * 4 + r) * ENL + i0 + ti * 4;
        row[0] = v0; row[1] = v1; row[2] = v2; row[3] = v3;
    }
}

// ---------------------------------------------------------------------------
// Kernel 2: g_c[b][j][u] = sum_e de[b][j][e] * w_de[e][u] + tw[b][u]
// tw fused: threads 0..63 compute the 64 topic-bias dots for this u-tile.
// ---------------------------------------------------------------------------
__global__ void __launch_bounds__(256) k_c(
    const float* __restrict__ de, const float* __restrict__ w_de,
    const float* __restrict__ topics, const float* __restrict__ wt)
{
    const int b  = blockIdx.y;
    const int u0 = blockIdx.x * 64;
    __shared__ float As[16][68];  // [e][j]
    __shared__ float Bs[16][68];  // [e][u]
    __shared__ float tws[64];
    const float* deb = de + (size_t)b * DEL * EDIM;
    const int tid = threadIdx.x;
    const int tj = tid & 15;
    const int tu = tid >> 4;
    ull acc2[4][2] = {};

    // Topic bias for this u-tile (tiny: 64 dots of length 100)
    if (tid < 64) {
        float acc = 0.f;
        const float* wr = wt + (size_t)(u0 + tid) * TDIM;
        const float* tp = topics + b * TDIM;
        #pragma unroll 4
        for (int t = 0; t < TDIM; t++) acc = fmaf(tp[t], wr[t], acc);
        tws[tid] = acc;
    }

    for (int e0 = 0; e0 < EDIM; e0 += 16) {
        #pragma unroll
        for (int r = 0; r < 4; r++) {
            int l = tid + 256 * r;
            int e = l & 15, j = l >> 4;
            As[e][j] = deb[(size_t)j * EDIM + e0 + e];
        }
        #pragma unroll
        for (int r = 0; r < 4; r++) {
            int l = tid + 256 * r;
            int e = l >> 6, uu = l & 63;
            Bs[e][uu] = w_de[(size_t)(e0 + e) * UDIM + u0 + uu];
        }
        __syncthreads();
        #pragma unroll
        for (int k = 0; k < 16; k++) {
            const float4 av = *(const float4*)&As[k][tj * 4];
            const ull b01 = *(const ull*)&Bs[k][tu * 4];
            const ull b23 = *(const ull*)&Bs[k][tu * 4 + 2];
            ull pa0 = pack2(av.x, av.x), pa1 = pack2(av.y, av.y);
            ull pa2 = pack2(av.z, av.z), pa3 = pack2(av.w, av.w);
            acc2[0][0] = fma2(pa0, b01, acc2[0][0]); acc2[0][1] = fma2(pa0, b23, acc2[0][1]);
            acc2[1][0] = fma2(pa1, b01, acc2[1][0]); acc2[1][1] = fma2(pa1, b23, acc2[1][1]);
            acc2[2][0] = fma2(pa2, b01, acc2[2][0]); acc2[2][1] = fma2(pa2, b23, acc2[2][1]);
            acc2[3][0] = fma2(pa3, b01, acc2[3][0]); acc2[3][1] = fma2(pa3, b23, acc2[3][1]);
        }
        __syncthreads();
    }
    #pragma unroll
    for (int r = 0; r < 4; r++) {
        float v[4];
        unpack2(acc2[r][0], v[0], v[1]);
        unpack2(acc2[r][1], v[2], v[3]);
        int j = tj * 4 + r;
        #pragma unroll
        for (int c = 0; c < 4; c++) {
            int ul = tu * 4 + c;
            g_c[((size_t)b * DEL + j) * UDIM + u0 + ul] = v[c] + tws[ul];
        }
    }
}

// ---------------------------------------------------------------------------
// Kernel 3 (fused attention): block = (b, j0..j0+1)
// ---------------------------------------------------------------------------
__global__ void __launch_bounds__(512) k_attn(
    const float* __restrict__ en, const float* __restrict__ de,
    const float* __restrict__ nu, float* __restrict__ out)
{
    const int b  = blockIdx.y;
    const int j0 = blockIdx.x * JT;
    const int t  = threadIdx.x;

    __shared__ float4 css[UDIM];   // (c[j0][u], c[j0+1][u], nu[u], 0)
    __shared__ float2 red2[16];
    __shared__ float2 alph[ENL];

    const float* cb = g_c + ((size_t)b * DEL + j0) * UDIM;
    css[t] = make_float4(cb[t], cb[UDIM + t], nu[t], 0.f);
    __syncthreads();

    // Phase 1: mu for i = t, 2 j's. Strip-mined: 16 loads in flight.
    const float* ae = g_aeT + (size_t)b * UDIM * ENL + t;
    float m0 = 0.f, m1 = 0.f;
    for (int u0 = 0; u0 < UDIM; u0 += STRIP) {
        float a[STRIP];
        #pragma unroll
        for (int k = 0; k < STRIP; k++)
            a[k] = __ldg(ae + (size_t)(u0 + k) * ENL);
        #pragma unroll
        for (int k = 0; k < STRIP; k++) {
            float4 c4 = css[u0 + k];
            m0 = fmaf(c4.z, tanh_fast(a[k] + c4.x), m0);
            m1 = fmaf(c4.z, tanh_fast(a[k] + c4.y), m1);
        }
    }

    const int wid = t >> 5, lane = t & 31;

    // Block max
    float2 r = make_float2(m0, m1);
    #pragma unroll
    for (int o = 16; o; o >>= 1) {
        r.x = fmaxf(r.x, __shfl_xor_sync(0xffffffffu, r.x, o));
        r.y = fmaxf(r.y, __shfl_xor_sync(0xffffffffu, r.y, o));
    }
    if (lane == 0) red2[wid] = r;
    __syncthreads();
    float2 M = red2[0];
    #pragma unroll
    for (int w = 1; w < 16; w++) {
        float2 q = red2[w];
        M.x = fmaxf(M.x, q.x); M.y = fmaxf(M.y, q.y);
    }
    __syncthreads();  // before reusing red2

    float e0 = __expf(m0 - M.x);
    float e1 = __expf(m1 - M.y);

    // Block sum
    float2 s = make_float2(e0, e1);
    #pragma unroll
    for (int o = 16; o; o >>= 1) {
        s.x += __shfl_xor_sync(0xffffffffu, s.x, o);
        s.y += __shfl_xor_sync(0xffffffffu, s.y, o);
    }
    if (lane == 0) red2[wid] = s;
    __syncthreads();
    float2 S = red2[0];
    #pragma unroll
    for (int w = 1; w < 16; w++) {
        float2 q = red2[w];
        S.x += q.x; S.y += q.y;
    }

    float a0 = e0 / S.x, a1 = e1 / S.y;
    alph[t] = make_float2(a0, a1);

    // Output layout (flat tuple): [output | alphas | p_gen]
    float* alphas_out = out + BSZ * DEL * ENL;
    float* pgen_out   = out + 2 * BSZ * DEL * ENL;
    const int base = ((b * DEL + j0) * ENL) + t;
    alphas_out[base      ] = a0;
    alphas_out[base + ENL] = a1;
    pgen_out[base      ] = 1.f / (1.f + __expf(-m0));
    pgen_out[base + ENL] = 1.f / (1.f + __expf(-m1));
    __syncthreads();

    // Phase 2: sum_en[j][e=t] = sum_i alphas[j][i] * en[b][i][e], strip-mined.
    float s0 = 0.f, s1 = 0.f;
    const float* enb = en + (size_t)b * ENL * EDIM + t;
    for (int i0 = 0; i0 < ENL; i0 += STRIP) {
        float ev[STRIP];
        #pragma unroll
        for (int k = 0; k < STRIP; k++)
            ev[k] = __ldg(enb + (size_t)(i0 + k) * EDIM);
        #pragma unroll
        for (int k = 0; k < STRIP; k++) {
            float2 av = alph[i0 + k];
            s0 = fmaf(av.x, ev[k], s0);
            s1 = fmaf(av.y, ev[k], s1);
        }
    }
    const int ob = ((b * DEL + j0) * EDIM) + t;
    out[ob       ] = de[ob       ] + s0;
    out[ob + EDIM] = de[ob + EDIM] + s1;
}

// ---------------------------------------------------------------------------
extern "C" void kernel_launch(void* const* d_in, const int* in_sizes, int n_in,
                              void* d_out, int out_size)
{
    const float* en     = (const float*)d_in[0];
    const float* de     = (const float*)d_in[1];
    const float* topics = (const float*)d_in[2];
    const float* w_en   = (const float*)d_in[3];
    const float* w_de   = (const float*)d_in[4];
    const float* nu     = (const float*)d_in[5];
    const float* wt     = (const float*)d_in[6];
    float* out = (float*)d_out;

    k_gemm_aeT<<<dim3(ENL / 64, UDIM / 64, BSZ), 256>>>(en, w_en);
    k_c<<<dim3(UDIM / 64, BSZ), 256>>>(de, w_de, topics, wt);
    k_attn<<<dim3(DEL / JT, BSZ), 512>>>(en, de, nu, out);
}

// round 4
// speedup vs baseline: 1.4159x; 1.1074x over previous
#include <cuda_runtime.h>

// Problem shapes (fixed by the dataset)
#define BSZ  8
#define ENL  512   // encoder length
#define DEL  64    // decoder length
#define EDIM 512   // embedding
#define UDIM 512   // units
#define TDIM 100   // topics
#define JT   2     // decoder positions per block in fused kernel
#define STRIP 16   // load batching depth (MLP)

// Scratch (no cudaMalloc allowed)
__device__ float g_aeT[BSZ * UDIM * ENL];   // att_en transposed: [b][u][i]  (8 MB)
__device__ float g_c  [BSZ * DEL * UDIM];   // att_de + topic bias: [b][j][u] (1 MB)

typedef unsigned long long ull;

__device__ __forceinline__ float tanh_fast(float x) {
    float y;
    asm("tanh.approx.f32 %0, %1;" : "=f"(y) : "f"(x));
    return y;
}
__device__ __forceinline__ ull pack2(float x, float y) {
    ull r; asm("mov.b64 %0, {%1, %2};" : "=l"(r) : "f"(x), "f"(y)); return r;
}
__device__ __forceinline__ void unpack2(ull p, float& x, float& y) {
    asm("mov.b64 {%0, %1}, %2;" : "=f"(x), "=f"(y) : "l"(p));
}
__device__ __forceinline__ ull fma2(ull a, ull b, ull c) {
    ull d; asm("fma.rn.f32x2 %0, %1, %2, %3;" : "=l"(d) : "l"(a), "l"(b), "l"(c));
    return d;
}

// ---------------------------------------------------------------------------
// Kernel 1: g_aeT[b][u][i] = sum_e en[b][i][e] * w_en[e][u]
// 128x128 tile, BK=16, 256 threads, 8x8 microtile, f32x2 FMAs,
// double-buffered smem, LDG->compute->STS software pipeline.
// ---------------------------------------------------------------------------
__global__ void __launch_bounds__(256) k_gemm_aeT(
    const float* __restrict__ en, const float* __restrict__ w_en)
{
    const int b  = blockIdx.z;
    const int u0 = blockIdx.y * 128;
    const int i0 = blockIdx.x * 128;

    __shared__ float As[2][16][128];  // [e][u]  reads broadcast (ty-shared)
    __shared__ float Bs[2][16][132];  // [e][i]  pad 132 for write banks

    const int tid = threadIdx.x;
    const int tx = tid & 15;           // i micro index
    const int ty = tid >> 4;           // u micro index

    // A-load mapping: 128 u x 2 e per pass, 8 passes
    const int ua = tid & 127;
    const int ea = tid >> 7;
    // B-load mapping: 16 e x 16 i per pass, 8 passes
    const int eb = tid & 15;
    const int ib = tid >> 4;

    const float* enb = en + (size_t)b * ENL * EDIM;
    const float* pa = w_en + (size_t)ea * UDIM + u0 + ua;
    const float* pb = enb + (size_t)(i0 + ib) * EDIM + eb;

    ull acc[8][4] = {};

    // Prologue: tile 0 -> smem[0]
    #pragma unroll
    for (int p = 0; p < 8; p++)
        As[0][ea + 2 * p][ua] = pa[(size_t)(2 * p) * UDIM];
    #pragma unroll
    for (int p = 0; p < 8; p++)
        Bs[0][eb][ib + 16 * p] = pb[(size_t)(16 * p) * EDIM];
    __syncthreads();

    int s = 0;
    for (int t = 0; t < 32; t++) {
        float ra[8], rb[8];
        if (t < 31) {  // issue next tile's LDGs before compute
            const float* qa = pa + (size_t)(t + 1) * 16 * UDIM;
            const float* qb = pb + (t + 1) * 16;
            #pragma unroll
            for (int p = 0; p < 8; p++) ra[p] = qa[(size_t)(2 * p) * UDIM];
            #pragma unroll
            for (int p = 0; p < 8; p++) rb[p] = qb[(size_t)(16 * p) * EDIM];
        }
        #pragma unroll
        for (int k = 0; k < 16; k++) {
            const float4 a0 = *(const float4*)&As[s][k][ty * 8];
            const float4 a1 = *(const float4*)&As[s][k][ty * 8 + 4];
            const ull b0 = *(const ull*)&Bs[s][k][tx * 8];
            const ull b1 = *(const ull*)&Bs[s][k][tx * 8 + 2];
            const ull b2 = *(const ull*)&Bs[s][k][tx * 8 + 4];
            const ull b3 = *(const ull*)&Bs[s][k][tx * 8 + 6];
            ull p0 = pack2(a0.x, a0.x), p1 = pack2(a0.y, a0.y);
            ull p2 = pack2(a0.z, a0.z), p3 = pack2(a0.w, a0.w);
            ull p4 = pack2(a1.x, a1.x), p5 = pack2(a1.y, a1.y);
            ull p6 = pack2(a1.z, a1.z), p7 = pack2(a1.w, a1.w);
            acc[0][0]=fma2(p0,b0,acc[0][0]); acc[0][1]=fma2(p0,b1,acc[0][1]);
            acc[0][2]=fma2(p0,b2,acc[0][2]); acc[0][3]=fma2(p0,b3,acc[0][3]);
            acc[1][0]=fma2(p1,b0,acc[1][0]); acc[1][1]=fma2(p1,b1,acc[1][1]);
            acc[1][2]=fma2(p1,b2,acc[1][2]); acc[1][3]=fma2(p1,b3,acc[1][3]);
            acc[2][0]=fma2(p2,b0,acc[2][0]); acc[2][1]=fma2(p2,b1,acc[2][1]);
            acc[2][2]=fma2(p2,b2,acc[2][2]); acc[2][3]=fma2(p2,b3,acc[2][3]);
            acc[3][0]=fma2(p3,b0,acc[3][0]); acc[3][1]=fma2(p3,b1,acc[3][1]);
            acc[3][2]=fma2(p3,b2,acc[3][2]); acc[3][3]=fma2(p3,b3,acc[3][3]);
            acc[4][0]=fma2(p4,b0,acc[4][0]); acc[4][1]=fma2(p4,b1,acc[4][1]);
            acc[4][2]=fma2(p4,b2,acc[4][2]); acc[4][3]=fma2(p4,b3,acc[4][3]);
            acc[5][0]=fma2(p5,b0,acc[5][0]); acc[5][1]=fma2(p5,b1,acc[5][1]);
            acc[5][2]=fma2(p5,b2,acc[5][2]); acc[5][3]=fma2(p5,b3,acc[5][3]);
            acc[6][0]=fma2(p6,b0,acc[6][0]); acc[6][1]=fma2(p6,b1,acc[6][1]);
            acc[6][2]=fma2(p6,b2,acc[6][2]); acc[6][3]=fma2(p6,b3,acc[6][3]);
            acc[7][0]=fma2(p7,b0,acc[7][0]); acc[7][1]=fma2(p7,b1,acc[7][1]);
            acc[7][2]=fma2(p7,b2,acc[7][2]); acc[7][3]=fma2(p7,b3,acc[7][3]);
        }
        if (t < 31) {  // stash next tile after compute (LDG latency hidden)
            #pragma unroll
            for (int p = 0; p < 8; p++) As[s ^ 1][ea + 2 * p][ua] = ra[p];
            #pragma unroll
            for (int p = 0; p < 8; p++) Bs[s ^ 1][eb][ib + 16 * p] = rb[p];
        }
        __syncthreads();
        s ^= 1;
    }

    float* outp = g_aeT + (size_t)b * UDIM * ENL
                + (size_t)(u0 + ty * 8) * ENL + i0 + tx * 8;
    #pragma unroll
    for (int q = 0; q < 8; q++) {
        ull* row = (ull*)(outp + (size_t)q * ENL);
        row[0] = acc[q][0]; row[1] = acc[q][1];
        row[2] = acc[q][2]; row[3] = acc[q][3];
    }
}

// ---------------------------------------------------------------------------
// Kernel 2: g_c[b][j][u] = sum_e de[b][j][e] * w_de[e][u] + tw[b][u]
// ---------------------------------------------------------------------------
__global__ void __launch_bounds__(256) k_c(
    const float* __restrict__ de, const float* __restrict__ w_de,
    const float* __restrict__ topics, const float* __restrict__ wt)
{
    const int b  = blockIdx.y;
    const int u0 = blockIdx.x * 64;
    __shared__ float As[16][68];  // [e][j]
    __shared__ float Bs[16][68];  // [e][u]
    __shared__ float tws[64];
    const float* deb = de + (size_t)b * DEL * EDIM;
    const int tid = threadIdx.x;
    const int tj = tid & 15;
    const int tu = tid >> 4;
    ull acc2[4][2] = {};

    if (tid < 64) {
        float acc = 0.f;
        const float* wr = wt + (size_t)(u0 + tid) * TDIM;
        const float* tp = topics + b * TDIM;
        #pragma unroll 4
        for (int t = 0; t < TDIM; t++) acc = fmaf(tp[t], wr[t], acc);
        tws[tid] = acc;
    }

    for (int e0 = 0; e0 < EDIM; e0 += 16) {
        #pragma unroll
        for (int r = 0; r < 4; r++) {
            int l = tid + 256 * r;
            int e = l & 15, j = l >> 4;
            As[e][j] = deb[(size_t)j * EDIM + e0 + e];
        }
        #pragma unroll
        for (int r = 0; r < 4; r++) {
            int l = tid + 256 * r;
            int e = l >> 6, uu = l & 63;
            Bs[e][uu] = w_de[(size_t)(e0 + e) * UDIM + u0 + uu];
        }
        __syncthreads();
        #pragma unroll
        for (int k = 0; k < 16; k++) {
            const float4 av = *(const float4*)&As[k][tj * 4];
            const ull b01 = *(const ull*)&Bs[k][tu * 4];
            const ull b23 = *(const ull*)&Bs[k][tu * 4 + 2];
            ull pa0 = pack2(av.x, av.x), pa1 = pack2(av.y, av.y);
            ull pa2 = pack2(av.z, av.z), pa3 = pack2(av.w, av.w);
            acc2[0][0] = fma2(pa0, b01, acc2[0][0]); acc2[0][1] = fma2(pa0, b23, acc2[0][1]);
            acc2[1][0] = fma2(pa1, b01, acc2[1][0]); acc2[1][1] = fma2(pa1, b23, acc2[1][1]);
            acc2[2][0] = fma2(pa2, b01, acc2[2][0]); acc2[2][1] = fma2(pa2, b23, acc2[2][1]);
            acc2[3][0] = fma2(pa3, b01, acc2[3][0]); acc2[3][1] = fma2(pa3, b23, acc2[3][1]);
        }
        __syncthreads();
    }
    #pragma unroll
    for (int r = 0; r < 4; r++) {
        float v[4];
        unpack2(acc2[r][0], v[0], v[1]);
        unpack2(acc2[r][1], v[2], v[3]);
        int j = tj * 4 + r;
        #pragma unroll
        for (int c = 0; c < 4; c++) {
            int ul = tu * 4 + c;
            g_c[((size_t)b * DEL + j) * UDIM + u0 + ul] = v[c] + tws[ul];
        }
    }
}

// ---------------------------------------------------------------------------
// Kernel 3 (fused attention): block = (b, j0..j0+1)
// ---------------------------------------------------------------------------
__global__ void __launch_bounds__(512) k_attn(
    const float* __restrict__ en, const float* __restrict__ de,
    const float* __restrict__ nu, float* __restrict__ out)
{
    const int b  = blockIdx.y;
    const int j0 = blockIdx.x * JT;
    const int t  = threadIdx.x;

    __shared__ float4 css[UDIM];   // (c[j0][u], c[j0+1][u], nu[u], 0)
    __shared__ float2 red2[16];
    __shared__ float2 alph[ENL];

    const float* cb = g_c + ((size_t)b * DEL + j0) * UDIM;
    css[t] = make_float4(cb[t], cb[UDIM + t], nu[t], 0.f);
    __syncthreads();

    // Phase 1: mu for i = t, 2 j's. Strip-mined: 16 loads in flight.
    const float* ae = g_aeT + (size_t)b * UDIM * ENL + t;
    float m0 = 0.f, m1 = 0.f;
    for (int u0 = 0; u0 < UDIM; u0 += STRIP) {
        float a[STRIP];
        #pragma unroll
        for (int k = 0; k < STRIP; k++)
            a[k] = __ldg(ae + (size_t)(u0 + k) * ENL);
        #pragma unroll
        for (int k = 0; k < STRIP; k++) {
            float4 c4 = css[u0 + k];
            m0 = fmaf(c4.z, tanh_fast(a[k] + c4.x), m0);
            m1 = fmaf(c4.z, tanh_fast(a[k] + c4.y), m1);
        }
    }

    const int wid = t >> 5, lane = t & 31;

    float2 r = make_float2(m0, m1);
    #pragma unroll
    for (int o = 16; o; o >>= 1) {
        r.x = fmaxf(r.x, __shfl_xor_sync(0xffffffffu, r.x, o));
        r.y = fmaxf(r.y, __shfl_xor_sync(0xffffffffu, r.y, o));
    }
    if (lane == 0) red2[wid] = r;
    __syncthreads();
    float2 M = red2[0];
    #pragma unroll
    for (int w = 1; w < 16; w++) {
        float2 q = red2[w];
        M.x = fmaxf(M.x, q.x); M.y = fmaxf(M.y, q.y);
    }
    __syncthreads();

    float e0 = __expf(m0 - M.x);
    float e1 = __expf(m1 - M.y);

    float2 s = make_float2(e0, e1);
    #pragma unroll
    for (int o = 16; o; o >>= 1) {
        s.x += __shfl_xor_sync(0xffffffffu, s.x, o);
        s.y += __shfl_xor_sync(0xffffffffu, s.y, o);
    }
    if (lane == 0) red2[wid] = s;
    __syncthreads();
    float2 S = red2[0];
    #pragma unroll
    for (int w = 1; w < 16; w++) {
        float2 q = red2[w];
        S.x += q.x; S.y += q.y;
    }

    float a0 = e0 / S.x, a1 = e1 / S.y;
    alph[t] = make_float2(a0, a1);

    float* alphas_out = out + BSZ * DEL * ENL;
    float* pgen_out   = out + 2 * BSZ * DEL * ENL;
    const int base = ((b * DEL + j0) * ENL) + t;
    alphas_out[base      ] = a0;
    alphas_out[base + ENL] = a1;
    pgen_out[base      ] = 1.f / (1.f + __expf(-m0));
    pgen_out[base + ENL] = 1.f / (1.f + __expf(-m1));
    __syncthreads();

    // Phase 2: sum_en[j][e=t] = sum_i alphas[j][i] * en[b][i][e]
    float s0 = 0.f, s1 = 0.f;
    const float* enb = en + (size_t)b * ENL * EDIM + t;
    for (int i0 = 0; i0 < ENL; i0 += STRIP) {
        float ev[STRIP];
        #pragma unroll
        for (int k = 0; k < STRIP; k++)
            ev[k] = __ldg(enb + (size_t)(i0 + k) * EDIM);
        #pragma unroll
        for (int k = 0; k < STRIP; k++) {
            float2 av = alph[i0 + k];
            s0 = fmaf(av.x, ev[k], s0);
            s1 = fmaf(av.y, ev[k], s1);
        }
    }
    const int ob = ((b * DEL + j0) * EDIM) + t;
    out[ob       ] = de[ob       ] + s0;
    out[ob + EDIM] = de[ob + EDIM] + s1;
}

// ---------------------------------------------------------------------------
extern "C" void kernel_launch(void* const* d_in, const int* in_sizes, int n_in,
                              void* d_out, int out_size)
{
    const float* en     = (const float*)d_in[0];
    const float* de     = (const float*)d_in[1];
    const float* topics = (const float*)d_in[2];
    const float* w_en   = (const float*)d_in[3];
    const float* w_de   = (const float*)d_in[4];
    const float* nu     = (const float*)d_in[5];
    const float* wt     = (const float*)d_in[6];
    float* out = (float*)d_out;

    k_gemm_aeT<<<dim3(ENL / 128, UDIM / 128, BSZ), 256>>>(en, w_en);
    k_c<<<dim3(UDIM / 64, BSZ), 256>>>(de, w_de, topics, wt);
    k_attn<<<dim3(DEL / JT, BSZ), 512>>>(en, de, nu, out);
}